// round 14
// baseline (speedup 1.0000x reference)
#include <cuda_runtime.h>
#include <math.h>

// Device-global accumulators. g_sum starts 0 (static init); finalize resets it
// after reading so every graph replay sees 0. g_loss_r overwritten every launch.
__device__ double g_sum = 0.0;
__device__ float  g_loss_r = 0.0f;

__device__ __forceinline__ float fast_sqrtf(float x)
{
    float r;
    asm("sqrt.approx.f32 %0, %1;" : "=f"(r) : "f"(x));
    return r;
}

// ---------------------------------------------------------------------------
// Grid distance: nearest cell (round-half-even = jnp.round), integer clamp,
// gather 3 floats, return |tp - cp|.  Index math: rn(fmaf(t, s, b)).
// ---------------------------------------------------------------------------
__device__ __forceinline__ float grid_dist(float tx, float ty, float tz,
                                           const float* __restrict__ grid,
                                           float bx, float by, float bz,
                                           float sx, float sy, float sz,
                                           int Rm1, unsigned strideX, unsigned strideY)
{
    int ix = __float2int_rn(fmaf(tx, sx, bx));
    int iy = __float2int_rn(fmaf(ty, sy, by));
    int iz = __float2int_rn(fmaf(tz, sz, bz));
    ix = min(max(ix, 0), Rm1);
    iy = min(max(iy, 0), Rm1);
    iz = min(max(iz, 0), Rm1);
    unsigned off = (unsigned)ix * strideX + (unsigned)iy * strideY + (unsigned)iz * 3u;
    float cx = __ldg(grid + off);
    float cy = __ldg(grid + off + 1u);
    float cz = __ldg(grid + off + 2u);
    float dx = tx - cx, dy = ty - cy, dz = tz - cz;
    return fast_sqrtf(fmaf(dx, dx, fmaf(dy, dy, dz * dz)));
}

// ---------------------------------------------------------------------------
// All 6 transforms + gathers for one point.
// ---------------------------------------------------------------------------
__device__ __forceinline__ float point_loss(float px, float py, float pz,
                                            const float4* __restrict__ planes4,
                                            const float4* __restrict__ axes4,
                                            const float* __restrict__ grid,
                                            float bx, float by, float bz,
                                            float sx, float sy, float sz,
                                            int Rm1, unsigned strideX, unsigned strideY)
{
    float acc = 0.f;

    #pragma unroll
    for (int k = 0; k < 3; k++) {
        float4 pl = __ldg(planes4 + k);
        float proj = px * pl.x + py * pl.y + pz * pl.z + pl.w;
        float rx = px - 2.f * proj * pl.x;
        float ry = py - 2.f * proj * pl.y;
        float rz = pz - 2.f * proj * pl.z;
        acc += grid_dist(rx, ry, rz, grid, bx, by, bz, sx, sy, sz, Rm1, strideX, strideY);
    }

    #pragma unroll
    for (int k = 0; k < 3; k++) {
        float4 q = __ldg(axes4 + k);
        float w = q.x, x = q.y, y = q.z, z = q.w;
        float tw = -x * px - y * py - z * pz;
        float qx =  w * px + y * pz - z * py;
        float qy =  w * py - x * pz + z * px;
        float qz =  w * pz + x * py - y * px;
        float rx = -tw * x + qx * w - qy * z + qz * y;
        float ry = -tw * y + qx * z + qy * w - qz * x;
        float rz = -tw * z - qx * y + qy * x + qz * w;
        acc += grid_dist(rx, ry, rz, grid, bx, by, bz, sx, sy, sz, Rm1, strideX, strideY);
    }

    return acc;
}

// ---------------------------------------------------------------------------
// Persistent main kernel: 6 blocks/SM * 148 SMs, grid-stride (~4.4 iters),
// one block reduction + one double atomic per block.
// ---------------------------------------------------------------------------
__global__ void __launch_bounds__(256, 6)
main_kernel(const float* __restrict__ pts,
            const float4* __restrict__ planes4,
            const float4* __restrict__ axes4,
            const float* __restrict__ grid,
            const float* __restrict__ gmin,
            const float* __restrict__ gmax,
            int N, int R)
{
    float gx = __ldg(gmin), gy = __ldg(gmin + 1), gz = __ldg(gmin + 2);
    float sx = (float)(R - 1) / (__ldg(gmax)     - gx);
    float sy = (float)(R - 1) / (__ldg(gmax + 1) - gy);
    float sz = (float)(R - 1) / (__ldg(gmax + 2) - gz);
    float bx = -gx * sx, by = -gy * sy, bz = -gz * sz;
    unsigned strideY = (unsigned)(R * 3);
    unsigned strideX = strideY * (unsigned)R;
    int Rm1 = R - 1;

    int tid     = blockIdx.x * blockDim.x + threadIdx.x;
    int nthread = gridDim.x * blockDim.x;

    float local = 0.f;

    for (int i = tid; i < N; i += nthread) {
        float px = __ldg(pts + 3 * i);
        float py = __ldg(pts + 3 * i + 1);
        float pz = __ldg(pts + 3 * i + 2);
        local += point_loss(px, py, pz, planes4, axes4, grid,
                            bx, by, bz, sx, sy, sz, Rm1, strideX, strideY);
    }

    // Warp reduce
    #pragma unroll
    for (int off = 16; off > 0; off >>= 1)
        local += __shfl_down_sync(0xFFFFFFFFu, local, off);

    // Block reduce
    __shared__ float warp_sums[8];
    int lane = threadIdx.x & 31;
    int wid  = threadIdx.x >> 5;
    if (lane == 0) warp_sums[wid] = local;
    __syncthreads();
    if (wid == 0) {
        float s = (lane < 8) ? warp_sums[lane] : 0.f;
        #pragma unroll
        for (int off = 4; off > 0; off >>= 1)
            s += __shfl_down_sync(0xFFFFFFFFu, s, off);
        if (lane == 0)
            atomicAdd(&g_sum, (double)s);
    }

    // Regularizer (independent of the reduction): one thread computes it.
    if (blockIdx.x == 0 && threadIdx.x == 0) {
        float n[3][3], v[3][3];
        #pragma unroll
        for (int r = 0; r < 3; r++) {
            float4 pl = __ldg(planes4 + r);
            n[r][0] = pl.x; n[r][1] = pl.y; n[r][2] = pl.z;
            float4 q = __ldg(axes4 + r);
            float nrm = sqrtf(q.y * q.y + q.z * q.z + q.w * q.w);
            float inv = 1.f / fmaxf(nrm, 1e-12f);
            v[r][0] = q.y * inv; v[r][1] = q.z * inv; v[r][2] = q.w * inv;
        }
        float sumA2 = 0.f, sumB2 = 0.f;
        #pragma unroll
        for (int r = 0; r < 3; r++)
            #pragma unroll
            for (int c = 0; c < 3; c++) {
                float da = n[r][0] * n[c][0] + n[r][1] * n[c][1] + n[r][2] * n[c][2]
                         - (r == c ? 1.f : 0.f);
                float db = v[r][0] * v[c][0] + v[r][1] * v[c][1] + v[r][2] * v[c][2]
                         - (r == c ? 1.f : 0.f);
                sumA2 += da * da;
                sumB2 += db * db;
            }
        g_loss_r = sumA2 + sumB2;
    }
}

// ---------------------------------------------------------------------------
// Finalize (1 thread): read accumulators, write outputs, reset for replay.
// ---------------------------------------------------------------------------
__global__ void finalize_kernel(float* __restrict__ out, int out_size, int N)
{
    double total = g_sum;
    g_sum = 0.0;   // reset for next graph replay
    float loss_r = g_loss_r;

    float sd  = (float)(total / (double)N);
    float fin = sd + 25.0f * loss_r;
    out[0] = fin;
    if (out_size > 1) out[1] = sd;
    if (out_size > 2) out[2] = loss_r;
}

// ---------------------------------------------------------------------------
extern "C" void kernel_launch(void* const* d_in, const int* in_sizes, int n_in,
                              void* d_out, int out_size)
{
    const float* planes = (const float*)d_in[0];   // (1,3,4)
    const float* axes   = (const float*)d_in[1];   // (1,3,4)
    const float* pts    = (const float*)d_in[2];   // (N,3)
    const float* grid   = (const float*)d_in[3];   // (R,R,R,3)
    const float* gmin   = (const float*)d_in[4];   // (3,)
    const float* gmax   = (const float*)d_in[5];   // (3,)

    int N = in_sizes[2] / 3;
    long gelems = (long)in_sizes[3] / 3;
    int R = (int)llrintf(cbrtf((float)gelems));

    // Persistent: fill the chip exactly — 6 blocks/SM * 148 SMs.
    int threads = 256;
    int blocks  = 6 * 148;
    int maxBlocks = (N + threads - 1) / threads;
    if (blocks > maxBlocks) blocks = maxBlocks;

    main_kernel<<<blocks, threads>>>(pts, (const float4*)planes,
                                     (const float4*)axes, grid, gmin, gmax, N, R);
    finalize_kernel<<<1, 1>>>((float*)d_out, out_size, N);
}

// round 15
// speedup vs baseline: 1.1795x; 1.1795x over previous
#include <cuda_runtime.h>
#include <math.h>

// Device-global accumulators. g_sum starts 0 (static init); finalize resets it
// after reading so every graph replay sees 0. g_loss_r overwritten every launch.
__device__ double g_sum = 0.0;
__device__ float  g_loss_r = 0.0f;

// ---------------------------------------------------------------------------
// Grid distance: nearest cell (round-half-even = jnp.round), integer clamp,
// gather 3 floats, return |tp - cp|.  Index math: rn(fmaf(t, s, b)).
// IEEE sqrtf on purpose: approx-MUFU sqrt measured SLOWER (R13/R14) — the
// Newton refinement lands on the underutilized FMA pipe.
// ---------------------------------------------------------------------------
__device__ __forceinline__ float grid_dist(float tx, float ty, float tz,
                                           const float* __restrict__ grid,
                                           float bx, float by, float bz,
                                           float sx, float sy, float sz,
                                           int Rm1, unsigned strideX, unsigned strideY)
{
    int ix = __float2int_rn(fmaf(tx, sx, bx));
    int iy = __float2int_rn(fmaf(ty, sy, by));
    int iz = __float2int_rn(fmaf(tz, sz, bz));
    ix = min(max(ix, 0), Rm1);
    iy = min(max(iy, 0), Rm1);
    iz = min(max(iz, 0), Rm1);
    unsigned off = (unsigned)ix * strideX + (unsigned)iy * strideY + (unsigned)iz * 3u;
    float cx = __ldg(grid + off);
    float cy = __ldg(grid + off + 1u);
    float cz = __ldg(grid + off + 2u);
    float dx = tx - cx, dy = ty - cy, dz = tz - cz;
    return sqrtf(fmaf(dx, dx, fmaf(dy, dy, dz * dz)));
}

// ---------------------------------------------------------------------------
// All 6 transforms + gathers for one point.
// ---------------------------------------------------------------------------
__device__ __forceinline__ float point_loss(float px, float py, float pz,
                                            const float4* __restrict__ planes4,
                                            const float4* __restrict__ axes4,
                                            const float* __restrict__ grid,
                                            float bx, float by, float bz,
                                            float sx, float sy, float sz,
                                            int Rm1, unsigned strideX, unsigned strideY)
{
    float acc = 0.f;

    #pragma unroll
    for (int k = 0; k < 3; k++) {
        float4 pl = __ldg(planes4 + k);
        float proj = px * pl.x + py * pl.y + pz * pl.z + pl.w;
        float rx = px - 2.f * proj * pl.x;
        float ry = py - 2.f * proj * pl.y;
        float rz = pz - 2.f * proj * pl.z;
        acc += grid_dist(rx, ry, rz, grid, bx, by, bz, sx, sy, sz, Rm1, strideX, strideY);
    }

    #pragma unroll
    for (int k = 0; k < 3; k++) {
        float4 q = __ldg(axes4 + k);
        float w = q.x, x = q.y, y = q.z, z = q.w;
        float tw = -x * px - y * py - z * pz;
        float qx =  w * px + y * pz - z * py;
        float qy =  w * py - x * pz + z * px;
        float qz =  w * pz + x * py - y * px;
        float rx = -tw * x + qx * w - qy * z + qz * y;
        float ry = -tw * y + qx * z + qy * w - qz * x;
        float rz = -tw * z - qx * y + qy * x + qz * w;
        acc += grid_dist(rx, ry, rz, grid, bx, by, bz, sx, sy, sz, Rm1, strideX, strideY);
    }

    return acc;
}

// ---------------------------------------------------------------------------
// Persistent main kernel: 6 blocks/SM * 148 SMs, grid-stride (~4.4 iters),
// one block reduction + one double atomic per block. Point loads use __ldcs
// (evict-first streaming) so the once-read 12MB point array doesn't evict the
// gather-hot grid lines from L1.
// ---------------------------------------------------------------------------
__global__ void __launch_bounds__(256, 6)
main_kernel(const float* __restrict__ pts,
            const float4* __restrict__ planes4,
            const float4* __restrict__ axes4,
            const float* __restrict__ grid,
            const float* __restrict__ gmin,
            const float* __restrict__ gmax,
            int N, int R)
{
    float gx = __ldg(gmin), gy = __ldg(gmin + 1), gz = __ldg(gmin + 2);
    float sx = (float)(R - 1) / (__ldg(gmax)     - gx);
    float sy = (float)(R - 1) / (__ldg(gmax + 1) - gy);
    float sz = (float)(R - 1) / (__ldg(gmax + 2) - gz);
    float bx = -gx * sx, by = -gy * sy, bz = -gz * sz;
    unsigned strideY = (unsigned)(R * 3);
    unsigned strideX = strideY * (unsigned)R;
    int Rm1 = R - 1;

    int tid     = blockIdx.x * blockDim.x + threadIdx.x;
    int nthread = gridDim.x * blockDim.x;

    float local = 0.f;

    for (int i = tid; i < N; i += nthread) {
        float px = __ldcs(pts + 3 * i);        // streaming: read-once data
        float py = __ldcs(pts + 3 * i + 1);
        float pz = __ldcs(pts + 3 * i + 2);
        local += point_loss(px, py, pz, planes4, axes4, grid,
                            bx, by, bz, sx, sy, sz, Rm1, strideX, strideY);
    }

    // Warp reduce
    #pragma unroll
    for (int off = 16; off > 0; off >>= 1)
        local += __shfl_down_sync(0xFFFFFFFFu, local, off);

    // Block reduce
    __shared__ float warp_sums[8];
    int lane = threadIdx.x & 31;
    int wid  = threadIdx.x >> 5;
    if (lane == 0) warp_sums[wid] = local;
    __syncthreads();
    if (wid == 0) {
        float s = (lane < 8) ? warp_sums[lane] : 0.f;
        #pragma unroll
        for (int off = 4; off > 0; off >>= 1)
            s += __shfl_down_sync(0xFFFFFFFFu, s, off);
        if (lane == 0)
            atomicAdd(&g_sum, (double)s);
    }

    // Regularizer (independent of the reduction): one thread computes it.
    if (blockIdx.x == 0 && threadIdx.x == 0) {
        float n[3][3], v[3][3];
        #pragma unroll
        for (int r = 0; r < 3; r++) {
            float4 pl = __ldg(planes4 + r);
            n[r][0] = pl.x; n[r][1] = pl.y; n[r][2] = pl.z;
            float4 q = __ldg(axes4 + r);
            float nrm = sqrtf(q.y * q.y + q.z * q.z + q.w * q.w);
            float inv = 1.f / fmaxf(nrm, 1e-12f);
            v[r][0] = q.y * inv; v[r][1] = q.z * inv; v[r][2] = q.w * inv;
        }
        float sumA2 = 0.f, sumB2 = 0.f;
        #pragma unroll
        for (int r = 0; r < 3; r++)
            #pragma unroll
            for (int c = 0; c < 3; c++) {
                float da = n[r][0] * n[c][0] + n[r][1] * n[c][1] + n[r][2] * n[c][2]
                         - (r == c ? 1.f : 0.f);
                float db = v[r][0] * v[c][0] + v[r][1] * v[c][1] + v[r][2] * v[c][2]
                         - (r == c ? 1.f : 0.f);
                sumA2 += da * da;
                sumB2 += db * db;
            }
        g_loss_r = sumA2 + sumB2;
    }
}

// ---------------------------------------------------------------------------
// Finalize (1 thread): read accumulators, write outputs, reset for replay.
// ---------------------------------------------------------------------------
__global__ void finalize_kernel(float* __restrict__ out, int out_size, int N)
{
    double total = g_sum;
    g_sum = 0.0;   // reset for next graph replay
    float loss_r = g_loss_r;

    float sd  = (float)(total / (double)N);
    float fin = sd + 25.0f * loss_r;
    out[0] = fin;
    if (out_size > 1) out[1] = sd;
    if (out_size > 2) out[2] = loss_r;
}

// ---------------------------------------------------------------------------
extern "C" void kernel_launch(void* const* d_in, const int* in_sizes, int n_in,
                              void* d_out, int out_size)
{
    const float* planes = (const float*)d_in[0];   // (1,3,4)
    const float* axes   = (const float*)d_in[1];   // (1,3,4)
    const float* pts    = (const float*)d_in[2];   // (N,3)
    const float* grid   = (const float*)d_in[3];   // (R,R,R,3)
    const float* gmin   = (const float*)d_in[4];   // (3,)
    const float* gmax   = (const float*)d_in[5];   // (3,)

    int N = in_sizes[2] / 3;
    long gelems = (long)in_sizes[3] / 3;
    int R = (int)llrintf(cbrtf((float)gelems));

    // Persistent: fill the chip exactly — 6 blocks/SM * 148 SMs.
    int threads = 256;
    int blocks  = 6 * 148;
    int maxBlocks = (N + threads - 1) / threads;
    if (blocks > maxBlocks) blocks = maxBlocks;

    main_kernel<<<blocks, threads>>>(pts, (const float4*)planes,
                                     (const float4*)axes, grid, gmin, gmax, N, R);
    finalize_kernel<<<1, 1>>>((float*)d_out, out_size, N);
}

// round 16
// speedup vs baseline: 1.2637x; 1.0714x over previous
#include <cuda_runtime.h>
#include <math.h>

// Device-global accumulators. g_sum starts 0 (static init); finalize resets it
// after reading so every graph replay sees 0. g_loss_r overwritten every launch.
__device__ double g_sum = 0.0;
__device__ float  g_loss_r = 0.0f;

// ---------------------------------------------------------------------------
// Grid distance: nearest cell (round-half-even = jnp.round), integer clamp,
// gather 12B via ONE aligned LDG.64 + ONE LDG.32 (covers both parities),
// return |tp - cp|.  IEEE sqrtf on purpose (approx-MUFU measured slower).
// ---------------------------------------------------------------------------
__device__ __forceinline__ float grid_dist(float tx, float ty, float tz,
                                           const float* __restrict__ grid,
                                           const float2* __restrict__ grid2,
                                           float bx, float by, float bz,
                                           float sx, float sy, float sz,
                                           int Rm1, unsigned strideX, unsigned strideY)
{
    int ix = __float2int_rn(fmaf(tx, sx, bx));
    int iy = __float2int_rn(fmaf(ty, sy, by));
    int iz = __float2int_rn(fmaf(tz, sz, bz));
    ix = min(max(ix, 0), Rm1);
    iy = min(max(iy, 0), Rm1);
    iz = min(max(iz, 0), Rm1);
    unsigned off = (unsigned)ix * strideX + (unsigned)iy * strideY + (unsigned)iz * 3u;

    // Even off: float2 at off/2, float at off+2.  Odd off: float at off,
    // float2 at (off+1)/2.  (off+1)>>1 equals off>>1 when even, (off+1)/2 when odd.
    bool odd = (off & 1u) != 0u;
    unsigned h   = (off + 1u) >> 1;            // float2 index of the 8B-aligned pair
    unsigned s32 = odd ? off : off + 2u;       // scalar float index
    float2 v = __ldg(grid2 + h);
    float  w = __ldg(grid + s32);

    float cx = odd ? w   : v.x;
    float cy = odd ? v.x : v.y;
    float cz = odd ? v.y : w;

    float dx = tx - cx, dy = ty - cy, dz = tz - cz;
    return sqrtf(fmaf(dx, dx, fmaf(dy, dy, dz * dz)));
}

// ---------------------------------------------------------------------------
// All 6 transforms + gathers for one point.
// ---------------------------------------------------------------------------
__device__ __forceinline__ float point_loss(float px, float py, float pz,
                                            const float4* __restrict__ planes4,
                                            const float4* __restrict__ axes4,
                                            const float* __restrict__ grid,
                                            const float2* __restrict__ grid2,
                                            float bx, float by, float bz,
                                            float sx, float sy, float sz,
                                            int Rm1, unsigned strideX, unsigned strideY)
{
    float acc = 0.f;

    #pragma unroll
    for (int k = 0; k < 3; k++) {
        float4 pl = __ldg(planes4 + k);
        float proj = px * pl.x + py * pl.y + pz * pl.z + pl.w;
        float rx = px - 2.f * proj * pl.x;
        float ry = py - 2.f * proj * pl.y;
        float rz = pz - 2.f * proj * pl.z;
        acc += grid_dist(rx, ry, rz, grid, grid2, bx, by, bz, sx, sy, sz, Rm1, strideX, strideY);
    }

    #pragma unroll
    for (int k = 0; k < 3; k++) {
        float4 q = __ldg(axes4 + k);
        float w = q.x, x = q.y, y = q.z, z = q.w;
        float tw = -x * px - y * py - z * pz;
        float qx =  w * px + y * pz - z * py;
        float qy =  w * py - x * pz + z * px;
        float qz =  w * pz + x * py - y * px;
        float rx = -tw * x + qx * w - qy * z + qz * y;
        float ry = -tw * y + qx * z + qy * w - qz * x;
        float rz = -tw * z - qx * y + qy * x + qz * w;
        acc += grid_dist(rx, ry, rz, grid, grid2, bx, by, bz, sx, sy, sz, Rm1, strideX, strideY);
    }

    return acc;
}

// ---------------------------------------------------------------------------
// Persistent main kernel: 6 blocks/SM * 148 SMs, grid-stride (~4.4 iters),
// one block reduction + one double atomic per block. Point loads use __ldcs.
// ---------------------------------------------------------------------------
__global__ void __launch_bounds__(256, 6)
main_kernel(const float* __restrict__ pts,
            const float4* __restrict__ planes4,
            const float4* __restrict__ axes4,
            const float* __restrict__ grid,
            const float* __restrict__ gmin,
            const float* __restrict__ gmax,
            int N, int R)
{
    const float2* __restrict__ grid2 = (const float2*)grid;

    float gx = __ldg(gmin), gy = __ldg(gmin + 1), gz = __ldg(gmin + 2);
    float sx = (float)(R - 1) / (__ldg(gmax)     - gx);
    float sy = (float)(R - 1) / (__ldg(gmax + 1) - gy);
    float sz = (float)(R - 1) / (__ldg(gmax + 2) - gz);
    float bx = -gx * sx, by = -gy * sy, bz = -gz * sz;
    unsigned strideY = (unsigned)(R * 3);
    unsigned strideX = strideY * (unsigned)R;
    int Rm1 = R - 1;

    int tid     = blockIdx.x * blockDim.x + threadIdx.x;
    int nthread = gridDim.x * blockDim.x;

    float local = 0.f;

    for (int i = tid; i < N; i += nthread) {
        float px = __ldcs(pts + 3 * i);        // streaming: read-once data
        float py = __ldcs(pts + 3 * i + 1);
        float pz = __ldcs(pts + 3 * i + 2);
        local += point_loss(px, py, pz, planes4, axes4, grid, grid2,
                            bx, by, bz, sx, sy, sz, Rm1, strideX, strideY);
    }

    // Warp reduce
    #pragma unroll
    for (int off = 16; off > 0; off >>= 1)
        local += __shfl_down_sync(0xFFFFFFFFu, local, off);

    // Block reduce
    __shared__ float warp_sums[8];
    int lane = threadIdx.x & 31;
    int wid  = threadIdx.x >> 5;
    if (lane == 0) warp_sums[wid] = local;
    __syncthreads();
    if (wid == 0) {
        float s = (lane < 8) ? warp_sums[lane] : 0.f;
        #pragma unroll
        for (int off = 4; off > 0; off >>= 1)
            s += __shfl_down_sync(0xFFFFFFFFu, s, off);
        if (lane == 0)
            atomicAdd(&g_sum, (double)s);
    }

    // Regularizer (independent of the reduction): one thread computes it.
    if (blockIdx.x == 0 && threadIdx.x == 0) {
        float n[3][3], v[3][3];
        #pragma unroll
        for (int r = 0; r < 3; r++) {
            float4 pl = __ldg(planes4 + r);
            n[r][0] = pl.x; n[r][1] = pl.y; n[r][2] = pl.z;
            float4 q = __ldg(axes4 + r);
            float nrm = sqrtf(q.y * q.y + q.z * q.z + q.w * q.w);
            float inv = 1.f / fmaxf(nrm, 1e-12f);
            v[r][0] = q.y * inv; v[r][1] = q.z * inv; v[r][2] = q.w * inv;
        }
        float sumA2 = 0.f, sumB2 = 0.f;
        #pragma unroll
        for (int r = 0; r < 3; r++)
            #pragma unroll
            for (int c = 0; c < 3; c++) {
                float da = n[r][0] * n[c][0] + n[r][1] * n[c][1] + n[r][2] * n[c][2]
                         - (r == c ? 1.f : 0.f);
                float db = v[r][0] * v[c][0] + v[r][1] * v[c][1] + v[r][2] * v[c][2]
                         - (r == c ? 1.f : 0.f);
                sumA2 += da * da;
                sumB2 += db * db;
            }
        g_loss_r = sumA2 + sumB2;
    }
}

// ---------------------------------------------------------------------------
// Finalize (1 thread): read accumulators, write outputs, reset for replay.
// ---------------------------------------------------------------------------
__global__ void finalize_kernel(float* __restrict__ out, int out_size, int N)
{
    double total = g_sum;
    g_sum = 0.0;   // reset for next graph replay
    float loss_r = g_loss_r;

    float sd  = (float)(total / (double)N);
    float fin = sd + 25.0f * loss_r;
    out[0] = fin;
    if (out_size > 1) out[1] = sd;
    if (out_size > 2) out[2] = loss_r;
}

// ---------------------------------------------------------------------------
extern "C" void kernel_launch(void* const* d_in, const int* in_sizes, int n_in,
                              void* d_out, int out_size)
{
    const float* planes = (const float*)d_in[0];   // (1,3,4)
    const float* axes   = (const float*)d_in[1];   // (1,3,4)
    const float* pts    = (const float*)d_in[2];   // (N,3)
    const float* grid   = (const float*)d_in[3];   // (R,R,R,3)
    const float* gmin   = (const float*)d_in[4];   // (3,)
    const float* gmax   = (const float*)d_in[5];   // (3,)

    int N = in_sizes[2] / 3;
    long gelems = (long)in_sizes[3] / 3;
    int R = (int)llrintf(cbrtf((float)gelems));

    // Persistent: fill the chip exactly — 6 blocks/SM * 148 SMs.
    int threads = 256;
    int blocks  = 6 * 148;
    int maxBlocks = (N + threads - 1) / threads;
    if (blocks > maxBlocks) blocks = maxBlocks;

    main_kernel<<<blocks, threads>>>(pts, (const float4*)planes,
                                     (const float4*)axes, grid, gmin, gmax, N, R);
    finalize_kernel<<<1, 1>>>((float*)d_out, out_size, N);
}